// round 1
// baseline (speedup 1.0000x reference)
#include <cuda_runtime.h>
#include <cuda_bf16.h>

// Problem constants
#define D        64
#define K        1024
#define NVEC     65536                  // 64*32*32
#define QELEMS   (NVEC * D)             // 4194304 quantized floats
#define TK       128                    // codewords per smem tile
#define BLOCK    256
#define GRID     128                    // GRID*BLOCK = 32768 threads, 2 vectors each

__device__ float g_enorm2[K];

// Kernel A: ||e_k||^2 for each codeword
__global__ void vq_enorm_kernel(const float* __restrict__ emb) {
    int k = blockIdx.x * blockDim.x + threadIdx.x;
    if (k < K) {
        const float4* row = reinterpret_cast<const float4*>(emb + (size_t)k * D);
        float s = 0.f;
#pragma unroll
        for (int i = 0; i < 16; i++) {
            float4 v = row[i];
            s += v.x * v.x + v.y * v.y + v.z * v.z + v.w * v.w;
        }
        g_enorm2[k] = s;
    }
}

// Kernel B: main VQ — argmin over codewords, gather, loss, indices
__global__ void __launch_bounds__(BLOCK) vq_main_kernel(
    const float* __restrict__ x,
    const float* __restrict__ emb,
    float* __restrict__ out,
    int out_size)
{
    __shared__ float4 se[TK * 16];   // 128 codewords x 64 floats = 32 KB
    __shared__ float  sn[TK];        // ||e||^2 tile

    const int v0 = blockIdx.x * BLOCK + threadIdx.x;  // first vector
    const int v1 = v0 + GRID * BLOCK;                 // second vector

    // Load both input vectors into registers (128 floats)
    float4 xa[16], xb[16];
    {
        const float4* ra = reinterpret_cast<const float4*>(x + (size_t)v0 * D);
        const float4* rb = reinterpret_cast<const float4*>(x + (size_t)v1 * D);
#pragma unroll
        for (int i = 0; i < 16; i++) { xa[i] = ra[i]; xb[i] = rb[i]; }
    }

    float best0 = 3.4e38f, best1 = 3.4e38f;
    int   bi0 = 0, bi1 = 0;

    for (int kt = 0; kt < K; kt += TK) {
        __syncthreads();
        // Cooperative tile load: TK codewords * 16 float4 each
        const float4* src = reinterpret_cast<const float4*>(emb + (size_t)kt * D);
        for (int i = threadIdx.x; i < TK * 16; i += BLOCK) se[i] = src[i];
        for (int i = threadIdx.x; i < TK; i += BLOCK) sn[i] = g_enorm2[kt + i];
        __syncthreads();

#pragma unroll 2
        for (int kk = 0; kk < TK; kk++) {
            float a0 = 0.f, a1 = 0.f, a2 = 0.f, a3 = 0.f;
            float b0 = 0.f, b1 = 0.f, b2 = 0.f, b3 = 0.f;
#pragma unroll
            for (int i = 0; i < 16; i++) {
                float4 e = se[kk * 16 + i];
                a0 += xa[i].x * e.x;  a1 += xa[i].y * e.y;
                a2 += xa[i].z * e.z;  a3 += xa[i].w * e.w;
                b0 += xb[i].x * e.x;  b1 += xb[i].y * e.y;
                b2 += xb[i].z * e.z;  b3 += xb[i].w * e.w;
            }
            float en = sn[kk];
            float d0 = en - 2.f * ((a0 + a1) + (a2 + a3));
            float d1 = en - 2.f * ((b0 + b1) + (b2 + b3));
            int kidx = kt + kk;
            if (d0 < best0) { best0 = d0; bi0 = kidx; }  // strict < keeps first min (argmin tie-break)
            if (d1 < best1) { best1 = d1; bi1 = kidx; }
        }
    }

    // Epilogue: gather winning codewords, write quantized output, accumulate loss
    float lsum = 0.f;
    {
        const float4* er = reinterpret_cast<const float4*>(emb + (size_t)bi0 * D);
        float4* o = reinterpret_cast<float4*>(out + (size_t)v0 * D);
#pragma unroll
        for (int i = 0; i < 16; i++) {
            float4 e = er[i]; float4 xx = xa[i];
            float dx = e.x - xx.x, dy = e.y - xx.y, dz = e.z - xx.z, dw = e.w - xx.w;
            lsum += dx * dx + dy * dy + dz * dz + dw * dw;
            float4 q;  // match reference: quantized = inputs + (quantized - inputs)
            q.x = xx.x + dx; q.y = xx.y + dy; q.z = xx.z + dz; q.w = xx.w + dw;
            o[i] = q;
        }
    }
    {
        const float4* er = reinterpret_cast<const float4*>(emb + (size_t)bi1 * D);
        float4* o = reinterpret_cast<float4*>(out + (size_t)v1 * D);
#pragma unroll
        for (int i = 0; i < 16; i++) {
            float4 e = er[i]; float4 xx = xb[i];
            float dx = e.x - xx.x, dy = e.y - xx.y, dz = e.z - xx.z, dw = e.w - xx.w;
            lsum += dx * dx + dy * dy + dz * dz + dw * dw;
            float4 q;
            q.x = xx.x + dx; q.y = xx.y + dy; q.z = xx.z + dz; q.w = xx.w + dw;
            o[i] = q;
        }
    }

    // Loss: 0.25 * mean((q - x)^2) over QELEMS elements.
    // Warp-reduce then one atomicAdd per warp onto out[QELEMS].
#pragma unroll
    for (int off = 16; off > 0; off >>= 1)
        lsum += __shfl_down_sync(0xffffffffu, lsum, off);
    if ((threadIdx.x & 31) == 0 && out_size > QELEMS)
        atomicAdd(out + QELEMS, lsum * (0.25f / (float)QELEMS));

    // Indices (as float, after quantized + loss)
    if (QELEMS + 1 + v0 < out_size) out[QELEMS + 1 + v0] = (float)bi0;
    if (QELEMS + 1 + v1 < out_size) out[QELEMS + 1 + v1] = (float)bi1;
}

extern "C" void kernel_launch(void* const* d_in, const int* in_sizes, int n_in,
                              void* d_out, int out_size) {
    const float* x   = (const float*)d_in[0];
    const float* emb = (const float*)d_in[1];
    // Defensive: identify tensors by size (inputs=4194304, embeddings=65536)
    if (n_in >= 2 && in_sizes[0] == K * D && in_sizes[1] == QELEMS) {
        const float* t = x; x = emb; emb = t;
    }
    float* out = (float*)d_out;

    if (out_size > QELEMS)
        cudaMemsetAsync(out + QELEMS, 0, sizeof(float), 0);  // zero loss accumulator

    vq_enorm_kernel<<<4, 256>>>(emb);
    vq_main_kernel<<<GRID, BLOCK>>>(x, emb, out, out_size);
}

// round 2
// speedup vs baseline: 1.0622x; 1.0622x over previous
#include <cuda_runtime.h>
#include <cuda_bf16.h>

#define D        64
#define K        1024
#define NVEC     65536                  // 64*32*32
#define QELEMS   (NVEC * D)             // 4194304 quantized floats
#define TK       128                    // codewords per smem tile
#define KSPLIT   4
#define KCHUNK   (K / KSPLIT)           // 256 codewords per block
#define BLOCK1   128                    // threads, dist kernel (V=2 vectors/thread)
#define VTILES   (NVEC / (BLOCK1 * 2))  // 256 vector tiles

__device__ float g_enorm2[K];
__device__ float g_best[KSPLIT][NVEC];
__device__ int   g_bidx[KSPLIT][NVEC];

// packed fp32x2 FMA / ADD (Blackwell; PTX-only)
__device__ __forceinline__ void fma2(unsigned long long& acc,
                                     unsigned long long a,
                                     unsigned long long b) {
    asm("fma.rn.f32x2 %0, %1, %2, %0;" : "+l"(acc) : "l"(a), "l"(b));
}
__device__ __forceinline__ unsigned long long add2(unsigned long long a,
                                                   unsigned long long b) {
    unsigned long long r;
    asm("add.rn.f32x2 %0, %1, %2;" : "=l"(r) : "l"(a), "l"(b));
    return r;
}
__device__ __forceinline__ float pairsum(unsigned long long a) {
    float2 f = *reinterpret_cast<float2*>(&a);
    return f.x + f.y;
}

// Kernel A: ||e_k||^2
__global__ void vq_enorm_kernel(const float* __restrict__ emb) {
    int k = blockIdx.x * blockDim.x + threadIdx.x;
    if (k < K) {
        const float4* row = reinterpret_cast<const float4*>(emb + (size_t)k * D);
        float s = 0.f;
#pragma unroll
        for (int i = 0; i < 16; i++) {
            float4 v = row[i];
            s += v.x * v.x + v.y * v.y + v.z * v.z + v.w * v.w;
        }
        g_enorm2[k] = s;
    }
}

// Kernel B: distance argmin over one K-split chunk for 256 vectors
__global__ void __launch_bounds__(BLOCK1) vq_dist_kernel(
    const float* __restrict__ x,
    const float* __restrict__ emb)
{
    __shared__ float4 se[TK * 16];   // 128 codewords x 64 floats = 32 KB
    __shared__ float  sn[TK];

    const int vt = blockIdx.x;       // vector tile
    const int ks = blockIdx.y;       // k-split
    const int v0 = vt * (BLOCK1 * 2) + threadIdx.x;
    const int v1 = v0 + BLOCK1;
    const int kb = ks * KCHUNK;

    // x vectors as packed f32x2 pairs (32 b64 each)
    unsigned long long xa2[32], xb2[32];
    {
        const ulonglong2* ra = reinterpret_cast<const ulonglong2*>(x + (size_t)v0 * D);
        const ulonglong2* rb = reinterpret_cast<const ulonglong2*>(x + (size_t)v1 * D);
#pragma unroll
        for (int i = 0; i < 16; i++) {
            ulonglong2 a = ra[i]; xa2[2*i] = a.x; xa2[2*i+1] = a.y;
            ulonglong2 b = rb[i]; xb2[2*i] = b.x; xb2[2*i+1] = b.y;
        }
    }

    float best0 = 3.4e38f, best1 = 3.4e38f;
    int   bi0 = kb, bi1 = kb;

    for (int kt = kb; kt < kb + KCHUNK; kt += TK) {
        __syncthreads();
        const float4* src = reinterpret_cast<const float4*>(emb + (size_t)kt * D);
        for (int i = threadIdx.x; i < TK * 16; i += BLOCK1) se[i] = src[i];
        for (int i = threadIdx.x; i < TK; i += BLOCK1) sn[i] = g_enorm2[kt + i];
        __syncthreads();

        const ulonglong2* te = reinterpret_cast<const ulonglong2*>(se);
#pragma unroll 2
        for (int kk = 0; kk < TK; kk++) {
            unsigned long long A0=0,A1=0,A2=0,A3=0,B0=0,B1=0,B2=0,B3=0;
#pragma unroll
            for (int i = 0; i < 16; i++) {
                ulonglong2 e = te[kk * 16 + i];   // 16B LDS, warp-broadcast
                if (i & 1) {
                    fma2(A2, xa2[2*i], e.x); fma2(A3, xa2[2*i+1], e.y);
                    fma2(B2, xb2[2*i], e.x); fma2(B3, xb2[2*i+1], e.y);
                } else {
                    fma2(A0, xa2[2*i], e.x); fma2(A1, xa2[2*i+1], e.y);
                    fma2(B0, xb2[2*i], e.x); fma2(B1, xb2[2*i+1], e.y);
                }
            }
            float en = sn[kk];
            float dotA = pairsum(add2(add2(A0, A1), add2(A2, A3)));
            float dotB = pairsum(add2(add2(B0, B1), add2(B2, B3)));
            float d0 = fmaf(-2.f, dotA, en);
            float d1 = fmaf(-2.f, dotB, en);
            int kidx = kt + kk;
            if (d0 < best0) { best0 = d0; bi0 = kidx; }  // strict <: first-min tie-break
            if (d1 < best1) { best1 = d1; bi1 = kidx; }
        }
    }

    g_best[ks][v0] = best0;  g_bidx[ks][v0] = bi0;
    g_best[ks][v1] = best1;  g_bidx[ks][v1] = bi1;
}

// Kernel C: combine splits, gather, write quantized + loss + indices
__global__ void __launch_bounds__(256) vq_final_kernel(
    const float* __restrict__ x,
    const float* __restrict__ emb,
    float* __restrict__ out,
    int out_size)
{
    const int v = blockIdx.x * blockDim.x + threadIdx.x;   // 0..NVEC-1

    float best = 3.4e38f; int bi = 0;
#pragma unroll
    for (int s = 0; s < KSPLIT; s++) {      // ascending split order → global first-min
        float b = g_best[s][v];
        int   k = g_bidx[s][v];
        if (b < best) { best = b; bi = k; }
    }

    float lsum = 0.f;
    {
        const float4* er = reinterpret_cast<const float4*>(emb + (size_t)bi * D);
        const float4* xr = reinterpret_cast<const float4*>(x + (size_t)v * D);
        float4* o = reinterpret_cast<float4*>(out + (size_t)v * D);
#pragma unroll
        for (int i = 0; i < 16; i++) {
            float4 e = er[i]; float4 xx = xr[i];
            float dx = e.x - xx.x, dy = e.y - xx.y, dz = e.z - xx.z, dw = e.w - xx.w;
            lsum += dx * dx + dy * dy + dz * dz + dw * dw;
            float4 q;   // match reference: quantized = x + (e - x)
            q.x = xx.x + dx; q.y = xx.y + dy; q.z = xx.z + dz; q.w = xx.w + dw;
            o[i] = q;
        }
    }

#pragma unroll
    for (int off = 16; off > 0; off >>= 1)
        lsum += __shfl_down_sync(0xffffffffu, lsum, off);
    if ((threadIdx.x & 31) == 0 && out_size > QELEMS)
        atomicAdd(out + QELEMS, lsum * (0.25f / (float)QELEMS));

    if (QELEMS + 1 + v < out_size) out[QELEMS + 1 + v] = (float)bi;
}

extern "C" void kernel_launch(void* const* d_in, const int* in_sizes, int n_in,
                              void* d_out, int out_size) {
    const float* x   = (const float*)d_in[0];
    const float* emb = (const float*)d_in[1];
    if (n_in >= 2 && in_sizes[0] == K * D && in_sizes[1] == QELEMS) {
        const float* t = x; x = emb; emb = t;
    }
    float* out = (float*)d_out;

    if (out_size > QELEMS)
        cudaMemsetAsync(out + QELEMS, 0, sizeof(float), 0);

    vq_enorm_kernel<<<4, 256>>>(emb);
    dim3 grid1(VTILES, KSPLIT);
    vq_dist_kernel<<<grid1, BLOCK1>>>(x, emb);
    vq_final_kernel<<<NVEC / 256, 256>>>(x, emb, out, out_size);
}

// round 4
// speedup vs baseline: 1.3378x; 1.2595x over previous
#include <cuda_runtime.h>
#include <cuda_bf16.h>
#include <cstdint>

#define D        64
#define K        1024
#define NVEC     65536
#define QELEMS   (NVEC * D)
#define MTILE    128
#define NCHUNK   64
#define NCHUNKS  (K / NCHUNK)     // 16
#define GRID     (NVEC / MTILE)   // 512
#define EPS      0.02f

// smem offsets for GEMM kernel
#define OFF_A   0            // 128 rows x 256B = 32768
#define OFF_B   32768        // 2 stages x 32768 (B1 16K + B2 16K per stage)
#define OFF_SN  98304        // 1024 floats = 4096
#define SMEM_SZ 102400

__device__ __nv_bfloat16 g_A [NVEC * 128];   // per vector: [h(64) | m(64)]
__device__ __nv_bfloat16 g_B1[K * 128];      // per codeword: [h | h]
__device__ __nv_bfloat16 g_B2[K * 128];      // per codeword: [m | m]
__device__ float g_enorm2[K];
__device__ int   g_bidx[NVEC];
__device__ int   g_flag_list[NVEC];
__device__ int   g_flag_count;

// ---------- helpers ----------
__device__ __forceinline__ uint32_t smem_u32(const void* p) {
    uint32_t a;
    asm("{ .reg .u64 t; cvta.to.shared.u64 t, %1; cvt.u32.u64 %0, t; }" : "=r"(a) : "l"(p));
    return a;
}
__device__ __forceinline__ void cp16(uint32_t dst, const void* src) {
    asm volatile("cp.async.cg.shared.global [%0], [%1], 16;" :: "r"(dst), "l"(src));
}
__device__ __forceinline__ void cp_commit() { asm volatile("cp.async.commit_group;" ::: "memory"); }
template<int N> __device__ __forceinline__ void cp_wait() {
    asm volatile("cp.async.wait_group %0;" :: "n"(N) : "memory");
}
__device__ __forceinline__ void ldsm4(uint32_t* r, uint32_t addr) {
    asm volatile("ldmatrix.sync.aligned.m8n8.x4.shared.b16 {%0,%1,%2,%3}, [%4];"
                 : "=r"(r[0]), "=r"(r[1]), "=r"(r[2]), "=r"(r[3]) : "r"(addr));
}
__device__ __forceinline__ void mma16816(float* c, const uint32_t* a, uint32_t b0, uint32_t b1) {
    asm volatile(
        "mma.sync.aligned.m16n8k16.row.col.f32.bf16.bf16.f32 "
        "{%0,%1,%2,%3}, {%4,%5,%6,%7}, {%8,%9}, {%0,%1,%2,%3};"
        : "+f"(c[0]), "+f"(c[1]), "+f"(c[2]), "+f"(c[3])
        : "r"(a[0]), "r"(a[1]), "r"(a[2]), "r"(a[3]), "r"(b0), "r"(b1));
}

// ---------- conversion kernels ----------
__global__ void __launch_bounds__(256) vq_convA(const float* __restrict__ x) {
    int v = blockIdx.x * 256 + threadIdx.x;
    const float4* xr = reinterpret_cast<const float4*>(x + (size_t)v * D);
    uint4* orow = reinterpret_cast<uint4*>(g_A + (size_t)v * 128);
#pragma unroll
    for (int i = 0; i < 8; i++) {
        float4 a = xr[2 * i], b = xr[2 * i + 1];
        float f[8] = {a.x, a.y, a.z, a.w, b.x, b.y, b.z, b.w};
        __nv_bfloat16 h[8], m[8];
#pragma unroll
        for (int e = 0; e < 8; e++) {
            h[e] = __float2bfloat16_rn(f[e]);
            m[e] = __float2bfloat16_rn(f[e] - __bfloat162float(h[e]));
        }
        orow[i]     = *reinterpret_cast<uint4*>(h);
        orow[8 + i] = *reinterpret_cast<uint4*>(m);
    }
}

__global__ void __launch_bounds__(256) vq_convE(const float* __restrict__ emb) {
    int k = blockIdx.x * 256 + threadIdx.x;
    if (blockIdx.x == 0 && threadIdx.x == 0) g_flag_count = 0;
    if (k >= K) return;
    const float4* er = reinterpret_cast<const float4*>(emb + (size_t)k * D);
    uint4* r1 = reinterpret_cast<uint4*>(g_B1 + (size_t)k * 128);
    uint4* r2 = reinterpret_cast<uint4*>(g_B2 + (size_t)k * 128);
    float s = 0.f;
#pragma unroll
    for (int i = 0; i < 8; i++) {
        float4 a = er[2 * i], b = er[2 * i + 1];
        float f[8] = {a.x, a.y, a.z, a.w, b.x, b.y, b.z, b.w};
        __nv_bfloat16 h[8], m[8];
#pragma unroll
        for (int e = 0; e < 8; e++) {
            s += f[e] * f[e];
            h[e] = __float2bfloat16_rn(f[e]);
            m[e] = __float2bfloat16_rn(f[e] - __bfloat162float(h[e]));
        }
        uint4 hv = *reinterpret_cast<uint4*>(h);
        uint4 mv = *reinterpret_cast<uint4*>(m);
        r1[i] = hv; r1[8 + i] = hv;      // [h | h]
        r2[i] = mv; r2[8 + i] = mv;      // [m | m]
    }
    g_enorm2[k] = s;
}

// load one B chunk (64 codewords, B1+B2) into stage
__device__ __forceinline__ void load_B(uint32_t sb, int chunk, int stage, int tid) {
    uint32_t base = sb + OFF_B + stage * 32768;
    const char* s1 = reinterpret_cast<const char*>(g_B1 + (size_t)chunk * NCHUNK * 128);
    const char* s2 = reinterpret_cast<const char*>(g_B2 + (size_t)chunk * NCHUNK * 128);
#pragma unroll
    for (int it = 0; it < 8; it++) {
        int i = tid + it * 256;                // 0..2047
        int mat = i >> 10;
        int rem = i & 1023;
        int row = rem >> 4, seg = rem & 15;    // row<64, seg<16 (16B units)
        const char* src = (mat ? s2 : s1) + row * 256 + seg * 16;
        cp16(base + mat * 16384 + row * 256 + ((seg ^ (row & 7)) << 4), src);
    }
}

// two-min update
#define UPD(dv, nn, B1v, I1v, B2v) \
    if ((dv) < (B1v)) { (B2v) = (B1v); (B1v) = (dv); (I1v) = (nn); } \
    else if ((dv) < (B2v)) { (B2v) = (dv); }

// ---------- main GEMM + argmin kernel ----------
__global__ void __launch_bounds__(256, 2) vq_gemm() {
    extern __shared__ char sm[];
    uint32_t sb = smem_u32(sm);
    const int tid = threadIdx.x, wid = tid >> 5, l = tid & 31;

    // prologue: A tile + e-norms + B chunks 0,1
    {
        const char* asrc = reinterpret_cast<const char*>(g_A + (size_t)blockIdx.x * MTILE * 128);
#pragma unroll
        for (int it = 0; it < 8; it++) {
            int i = tid + it * 256;            // 0..2047
            int row = i >> 4, seg = i & 15;
            cp16(sb + OFF_A + row * 256 + ((seg ^ (row & 7)) << 4), asrc + row * 256 + seg * 16);
        }
        cp16(sb + OFF_SN + tid * 16, reinterpret_cast<const char*>(g_enorm2) + tid * 16);
        load_B(sb, 0, 0, tid);
        cp_commit();                           // G0: A + sn + B0
        load_B(sb, 1, 1, tid);
        cp_commit();                           // G1: B1
    }
    cp_wait<1>();
    __syncthreads();

    // hoist A fragments for all 8 k-steps (reused for B1 and B2)
    uint32_t aF[8][4];
    {
        int row = (wid << 4) + (l & 15);
        uint32_t rb = sb + OFF_A + row * 256;
#pragma unroll
        for (int j = 0; j < 8; j++) {
            int seg = j * 2 + (l >> 4);
            ldsm4(aF[j], rb + ((seg ^ (row & 7)) << 4));
        }
    }
    const float* snp = reinterpret_cast<const float*>(sm + OFF_SN);

    float b1a = 3.4e38f, b2a = 3.4e38f, b1b = 3.4e38f, b2b = 3.4e38f;
    int i1a = 0, i1b = 0;

    for (int c = 0; c < NCHUNKS; c++) {
        if (c > 0) { cp_wait<1>(); __syncthreads(); }
        uint32_t stage = sb + OFF_B + (c & 1) * 32768;

        float C[8][4];
#pragma unroll
        for (int t = 0; t < 8; t++) { C[t][0] = C[t][1] = C[t][2] = C[t][3] = 0.f; }

#pragma unroll
        for (int mat = 0; mat < 2; mat++) {
            uint32_t bbase = stage + mat * 16384;
#pragma unroll
            for (int j = 0; j < 8; j++) {
#pragma unroll
                for (int g = 0; g < 4; g++) {
                    int row = (g << 4) + (l & 15);
                    int seg = j * 2 + (l >> 4);
                    uint32_t r[4];
                    ldsm4(r, bbase + row * 256 + ((seg ^ (row & 7)) << 4));
                    mma16816(C[2 * g],     aF[j], r[0], r[2]);
                    mma16816(C[2 * g + 1], aF[j], r[1], r[3]);
                }
            }
        }

        // epilogue: d = ||e||^2 - 2*dot, two-min tracking (ascending index order)
#pragma unroll
        for (int t = 0; t < 8; t++) {
            int n0 = c * NCHUNK + t * 8 + 2 * (l & 3);
            float s0 = snp[n0], s1 = snp[n0 + 1];
            float d;
            d = fmaf(-2.f, C[t][0], s0); UPD(d, n0,     b1a, i1a, b2a);
            d = fmaf(-2.f, C[t][1], s1); UPD(d, n0 + 1, b1a, i1a, b2a);
            d = fmaf(-2.f, C[t][2], s0); UPD(d, n0,     b1b, i1b, b2b);
            d = fmaf(-2.f, C[t][3], s1); UPD(d, n0 + 1, b1b, i1b, b2b);
        }

        __syncthreads();                       // all warps done reading stage c&1
        if (c + 2 < NCHUNKS) load_B(sb, c + 2, c & 1, tid);
        cp_commit();
    }

    // cross-lane merge within 4-lane groups (same row, interleaved cols)
#pragma unroll
    for (int off = 1; off <= 2; off <<= 1) {
        float p1 = __shfl_xor_sync(0xffffffffu, b1a, off);
        int   pi = __shfl_xor_sync(0xffffffffu, i1a, off);
        float p2 = __shfl_xor_sync(0xffffffffu, b2a, off);
        if (p1 < b1a || (p1 == b1a && pi < i1a)) { b2a = fminf(b1a, p2); b1a = p1; i1a = pi; }
        else                                      { b2a = fminf(b2a, p1); }
        p1 = __shfl_xor_sync(0xffffffffu, b1b, off);
        pi = __shfl_xor_sync(0xffffffffu, i1b, off);
        p2 = __shfl_xor_sync(0xffffffffu, b2b, off);
        if (p1 < b1b || (p1 == b1b && pi < i1b)) { b2b = fminf(b1b, p2); b1b = p1; i1b = pi; }
        else                                      { b2b = fminf(b2b, p1); }
    }

    if ((l & 3) == 0) {
        int v = blockIdx.x * MTILE + wid * 16 + (l >> 2);
        g_bidx[v] = i1a;
        if (b2a - b1a <= EPS) { int s = atomicAdd(&g_flag_count, 1); g_flag_list[s] = v; }
        g_bidx[v + 8] = i1b;
        if (b2b - b1b <= EPS) { int s = atomicAdd(&g_flag_count, 1); g_flag_list[s] = v + 8; }
    }
}

// ---------- exact rescan for flagged vectors ----------
__global__ void __launch_bounds__(256) vq_rescan(const float* __restrict__ x,
                                                 const float* __restrict__ emb) {
    __shared__ float sx[64];
    __shared__ float sbest[256];
    __shared__ int   sidx[256];
    int n = g_flag_count;
    if (n > NVEC) n = NVEC;
    for (int vi = blockIdx.x; vi < n; vi += gridDim.x) {
        int v = g_flag_list[vi];
        __syncthreads();
        if (threadIdx.x < 16)
            reinterpret_cast<float4*>(sx)[threadIdx.x] =
                reinterpret_cast<const float4*>(x + (size_t)v * D)[threadIdx.x];
        __syncthreads();
        float best = 3.4e38f; int bi = K;
        for (int k = threadIdx.x; k < K; k += 256) {
            const float4* er = reinterpret_cast<const float4*>(emb + (size_t)k * D);
            float dot = 0.f;
#pragma unroll
            for (int i = 0; i < 16; i++) {
                float4 e = er[i];
                dot += sx[4*i] * e.x + sx[4*i+1] * e.y + sx[4*i+2] * e.z + sx[4*i+3] * e.w;
            }
            float d = fmaf(-2.f, dot, g_enorm2[k]);
            if (d < best) { best = d; bi = k; }
        }
        sbest[threadIdx.x] = best; sidx[threadIdx.x] = bi;
        __syncthreads();
        for (int s = 128; s > 0; s >>= 1) {
            if (threadIdx.x < s) {
                float ob = sbest[threadIdx.x + s]; int oi = sidx[threadIdx.x + s];
                if (ob < sbest[threadIdx.x] ||
                    (ob == sbest[threadIdx.x] && oi < sidx[threadIdx.x])) {
                    sbest[threadIdx.x] = ob; sidx[threadIdx.x] = oi;
                }
            }
            __syncthreads();
        }
        if (threadIdx.x == 0) g_bidx[v] = sidx[0];
    }
}

// ---------- finalize: gather, quantized, loss, indices ----------
__global__ void __launch_bounds__(256) vq_final(const float* __restrict__ x,
                                                const float* __restrict__ emb,
                                                float* __restrict__ out, int out_size) {
    const int v = blockIdx.x * 256 + threadIdx.x;
    int bi = g_bidx[v];
    float lsum = 0.f;
    {
        const float4* er = reinterpret_cast<const float4*>(emb + (size_t)bi * D);
        const float4* xr = reinterpret_cast<const float4*>(x + (size_t)v * D);
        float4* o = reinterpret_cast<float4*>(out + (size_t)v * D);
#pragma unroll
        for (int i = 0; i < 16; i++) {
            float4 e = er[i]; float4 xx = xr[i];
            float dx = e.x - xx.x, dy = e.y - xx.y, dz = e.z - xx.z, dw = e.w - xx.w;
            lsum += dx * dx + dy * dy + dz * dz + dw * dw;
            float4 q;   // quantized = x + (e - x), matching reference arithmetic
            q.x = xx.x + dx; q.y = xx.y + dy; q.z = xx.z + dz; q.w = xx.w + dw;
            o[i] = q;
        }
    }
#pragma unroll
    for (int off = 16; off > 0; off >>= 1)
        lsum += __shfl_down_sync(0xffffffffu, lsum, off);
    if ((threadIdx.x & 31) == 0 && out_size > QELEMS)
        atomicAdd(out + QELEMS, lsum * (0.25f / (float)QELEMS));
    if (QELEMS + 1 + v < out_size) out[QELEMS + 1 + v] = (float)bi;
}

extern "C" void kernel_launch(void* const* d_in, const int* in_sizes, int n_in,
                              void* d_out, int out_size) {
    const float* x   = (const float*)d_in[0];
    const float* emb = (const float*)d_in[1];
    if (n_in >= 2 && in_sizes[0] == K * D && in_sizes[1] == QELEMS) {
        const float* t = x; x = emb; emb = t;
    }
    float* out = (float*)d_out;

    if (out_size > QELEMS)
        cudaMemsetAsync(out + QELEMS, 0, sizeof(float), 0);

    cudaFuncSetAttribute(vq_gemm, cudaFuncAttributeMaxDynamicSharedMemorySize, SMEM_SZ);

    vq_convA<<<NVEC / 256, 256>>>(x);
    vq_convE<<<4, 256>>>(emb);
    vq_gemm<<<GRID, 256, SMEM_SZ>>>();
    vq_rescan<<<128, 256>>>(x, emb);
    vq_final<<<NVEC / 256, 256>>>(x, emb, out, out_size);
}